// round 10
// baseline (speedup 1.0000x reference)
#include <cuda_runtime.h>
#include <cuda_bf16.h>
#include <math.h>
#include <stdint.h>

#define B_   2
#define T_   2048
#define C_   1024
#define H_   16
#define HD_  64
#define WIN_ 512
#define M_   (B_ * T_)

// ---------------------------------------------------------------------------
// Device scratch (allocation-free)
// ---------------------------------------------------------------------------
__device__ __nv_bfloat16 g_qh[(size_t)B_ * H_ * T_ * HD_];
__device__ __nv_bfloat16 g_ql[(size_t)B_ * H_ * T_ * HD_];
__device__ __nv_bfloat16 g_kh[(size_t)B_ * H_ * T_ * HD_];
__device__ __nv_bfloat16 g_kl[(size_t)B_ * H_ * T_ * HD_];
__device__ __nv_bfloat16 g_vh[(size_t)B_ * H_ * T_ * HD_];
__device__ __nv_bfloat16 g_vl[(size_t)B_ * H_ * T_ * HD_];

__device__ __nv_bfloat16 g_x_hi[(size_t)M_ * C_];
__device__ __nv_bfloat16 g_x_lo[(size_t)M_ * C_];
__device__ __nv_bfloat16 g_w_hi[(size_t)4 * C_ * C_];   // Wq,Wk,Wv,Wo stacked
__device__ __nv_bfloat16 g_w_lo[(size_t)4 * C_ * C_];
__device__ __nv_bfloat16 g_att_hi[(size_t)M_ * C_];
__device__ __nv_bfloat16 g_att_lo[(size_t)M_ * C_];

// ---------------------------------------------------------------------------
// PTX helpers — compute_80-compatible only
// ---------------------------------------------------------------------------
__device__ __forceinline__ uint32_t smem_u32(const void* p) {
    uint32_t a;
    asm("{ .reg .u64 t; cvta.to.shared.u64 t, %1; cvt.u32.u64 %0, t; }"
        : "=r"(a) : "l"(p));
    return a;
}

__device__ __forceinline__ void cp16(uint32_t s, const void* g) {
    asm volatile("cp.async.cg.shared.global [%0], [%1], 16;" :: "r"(s), "l"(g));
}
__device__ __forceinline__ void cp_commit() { asm volatile("cp.async.commit_group;"); }
__device__ __forceinline__ void cp_wait1()  { asm volatile("cp.async.wait_group 1;" ::: "memory"); }
__device__ __forceinline__ void cp_wait2()  { asm volatile("cp.async.wait_group 2;" ::: "memory"); }

__device__ __forceinline__ void ldmx4(uint32_t& r0, uint32_t& r1, uint32_t& r2, uint32_t& r3,
                                      uint32_t addr) {
    asm volatile("ldmatrix.sync.aligned.m8n8.x4.shared.b16 {%0,%1,%2,%3}, [%4];"
                 : "=r"(r0), "=r"(r1), "=r"(r2), "=r"(r3) : "r"(addr));
}
__device__ __forceinline__ void ldmx4t(uint32_t& r0, uint32_t& r1, uint32_t& r2, uint32_t& r3,
                                       uint32_t addr) {
    asm volatile("ldmatrix.sync.aligned.m8n8.x4.trans.shared.b16 {%0,%1,%2,%3}, [%4];"
                 : "=r"(r0), "=r"(r1), "=r"(r2), "=r"(r3) : "r"(addr));
}

// NOTE: NOT volatile — pure register function; lets ptxas schedule HMMAs to
// break accumulator RAW chains (round-9 stuck at tensor=57% from frozen order).
__device__ __forceinline__ void mma16816(float* c, const uint32_t* a, const uint32_t* b) {
    asm("mma.sync.aligned.m16n8k16.row.col.f32.bf16.bf16.f32 "
        "{%0,%1,%2,%3}, {%4,%5,%6,%7}, {%8,%9}, {%0,%1,%2,%3};"
        : "+f"(c[0]), "+f"(c[1]), "+f"(c[2]), "+f"(c[3])
        : "r"(a[0]), "r"(a[1]), "r"(a[2]), "r"(a[3]), "r"(b[0]), "r"(b[1]));
}

// pack two fp32 into bf16x2 (a -> low half, b -> high half)
__device__ __forceinline__ uint32_t pkbf2(float a, float b) {
    uint32_t r;
    asm("cvt.rn.bf16x2.f32 %0, %1, %2;" : "=r"(r) : "f"(b), "f"(a));
    return r;
}
// split (a,b) into hi pack + residual-lo pack
__device__ __forceinline__ void split2(float a, float b, uint32_t& hi, uint32_t& lo) {
    hi = pkbf2(a, b);
    const float ra = a - __uint_as_float(hi << 16);
    const float rb = b - __uint_as_float(hi & 0xFFFF0000u);
    lo = pkbf2(ra, rb);
}

// ---------------------------------------------------------------------------
// fp32 -> bf16 hi/lo split conversion (x and the 4 weight matrices)
// ---------------------------------------------------------------------------
__global__ __launch_bounds__(256)
void conv_kernel(const float* __restrict__ x,
                 const float* __restrict__ wq, const float* __restrict__ wk,
                 const float* __restrict__ wv, const float* __restrict__ wo)
{
    const int i = blockIdx.x * 256 + threadIdx.x;   // float4 index
    const float* src;
    __nv_bfloat16 *dhi, *dlo;
    size_t off;
    if (i < 1048576) {
        src = x + (size_t)i * 4;
        dhi = g_x_hi; dlo = g_x_lo; off = (size_t)i * 4;
    } else {
        const int r = i - 1048576;
        const int w = r >> 18;
        const float* ws = (w == 0) ? wq : (w == 1) ? wk : (w == 2) ? wv : wo;
        src = ws + (size_t)(r & 262143) * 4;
        dhi = g_w_hi; dlo = g_w_lo; off = (size_t)r * 4;
    }
    const float4 v = *(const float4*)src;
    uint32_t h0, l0, h1, l1;
    split2(v.x, v.y, h0, l0);
    split2(v.z, v.w, h1, l1);
    *(uint32_t*)(dhi + off)     = h0;
    *(uint32_t*)(dhi + off + 2) = h1;
    *(uint32_t*)(dlo + off)     = l0;
    *(uint32_t*)(dlo + off + 2) = l1;
}

// ---------------------------------------------------------------------------
// mma.sync GEMM, bf16 hi/lo split (3 MMAs).
// CTA tile 128(M) x 256(N), BK=32, 256 threads: 8 warps as 2(M) x 4(N),
// warp tile 64x64. MMA issue order cycles over the 4 mf-accumulators so the
// same accumulator is reused only every 8 MMAs (covers HMMA RAW latency).
// 3-stage pipeline, one __syncthreads per chunk. smem = 147456; 1 CTA/SM.
// MODE 0: out -> bf16 hi/lo q/k/v in [B,H,T,hd]; Q scaled by 1/8.
// MODE 1: A = g_att hi/lo, W = Wo; out = fp32 [M,C].
// ---------------------------------------------------------------------------
#define STG_BYTES 49152              // A(hi+lo) 16KB + B(hi+lo) 32KB
#define GEMM_SMEM (3 * STG_BYTES)    // 147456

template <int MODE>
__global__ void __launch_bounds__(256, 1)
gemm_mma(float* __restrict__ out)
{
    extern __shared__ char smem_raw[];
    const uint32_t smem = smem_u32(smem_raw);

    const int tid  = threadIdx.x;
    const int wid  = tid >> 5;
    const int lane = tid & 31;
    const int col0 = blockIdx.x * 256;
    const int row0 = blockIdx.y * 128;
    const int z    = blockIdx.z;

    const int wrow = wid & 1;        // M: 2 warps x 64
    const int wcol = wid >> 1;       // N: 4 warps x 64

    const __nv_bfloat16 *Ahi, *Alo;
    if (MODE == 0) { Ahi = g_x_hi;   Alo = g_x_lo;   }
    else           { Ahi = g_att_hi; Alo = g_att_lo; }
    const size_t woff = (MODE == 0 ? (size_t)z : 3) * ((size_t)C_ * C_);

    const __nv_bfloat16* a_hi = Ahi + (size_t)row0 * C_;
    const __nv_bfloat16* a_lo = Alo + (size_t)row0 * C_;
    const __nv_bfloat16* b_hi = g_w_hi + woff + (size_t)col0 * C_;
    const __nv_bfloat16* b_lo = g_w_lo + woff + (size_t)col0 * C_;

    // stage layout: Ahi @0 (8K), Alo @8192, Bhi @16384 (16K), Blo @32768 (16K)
    auto load_stage = [&](int chunk, int s) {
        const int k0 = chunk * 32;
        const uint32_t st = smem + (uint32_t)s * STG_BYTES;
#pragma unroll
        for (int half = 0; half < 2; half++) {          // A: 512 slots
            const int slot = tid + half * 256;
            const int rr = slot >> 2;                   // 0..127
            const int ch = slot & 3;
            const uint32_t so = (uint32_t)(rr * 64 + ((ch ^ ((rr >> 1) & 3)) << 4));
            const size_t   go = (size_t)rr * C_ + k0 + ch * 8;
            cp16(st +        so, a_hi + go);
            cp16(st + 8192 + so, a_lo + go);
        }
#pragma unroll
        for (int q = 0; q < 4; q++) {                   // B: 1024 slots
            const int slot = tid + q * 256;
            const int rr = slot >> 2;                   // 0..255
            const int ch = slot & 3;
            const uint32_t so = (uint32_t)(rr * 64 + ((ch ^ ((rr >> 1) & 3)) << 4));
            const size_t   go = (size_t)rr * C_ + k0 + ch * 8;
            cp16(st + 16384 + so, b_hi + go);
            cp16(st + 32768 + so, b_lo + go);
        }
        cp_commit();
    };

    float c[4][8][4];
#pragma unroll
    for (int mf = 0; mf < 4; mf++)
#pragma unroll
        for (int nf = 0; nf < 8; nf++)
#pragma unroll
            for (int e = 0; e < 4; e++) c[mf][nf][e] = 0.f;

    // ldmatrix lane pieces (row offset + swizzle key, bytes)
    const int      rA    = lane & 15;
    const uint32_t aRow  = (uint32_t)(rA * 64);
    const uint32_t aSw   = (uint32_t)(((rA >> 1) & 3) << 4);
    const uint32_t aCb   = (uint32_t)((lane >> 4) << 4);          // 0 or 16
    const int      rB    = (lane & 7) + ((lane & 16) >> 1);
    const uint32_t bRow  = (uint32_t)(rB * 64);
    const uint32_t bSw   = (uint32_t)(((rB >> 1) & 3) << 4);
    const uint32_t bCb   = (uint32_t)((lane & 8) << 1);           // 0 or 16

    load_stage(0, 0);
    load_stage(1, 1);

    for (int ck = 0; ck < 32; ck++) {
        cp_wait1();
        __syncthreads();
        if (ck + 2 < 32) load_stage(ck + 2, (ck + 2) % 3);
        else             cp_commit();                  // keep group count uniform

        const uint32_t st = smem + (uint32_t)(ck % 3) * STG_BYTES;
        const uint32_t Abase = st + (uint32_t)(wrow * 4096) + aRow;           // 64 rows
        const uint32_t Bbase = st + 16384 + (uint32_t)(wcol * 4096) + bRow;   // 64 rows

#pragma unroll
        for (int k16 = 0; k16 < 2; k16++) {
            const uint32_t ca = ((aCb + (uint32_t)(k16 * 32)) ^ aSw);
            const uint32_t cb = ((bCb + (uint32_t)(k16 * 32)) ^ bSw);
            uint32_t ah[4][4], al[4][4];
#pragma unroll
            for (int mf = 0; mf < 4; mf++) {
                const uint32_t a = Abase + (uint32_t)(mf * 1024) + ca;
                ldmx4(ah[mf][0], ah[mf][1], ah[mf][2], ah[mf][3], a);
                ldmx4(al[mf][0], al[mf][1], al[mf][2], al[mf][3], a + 8192);
            }
#pragma unroll
            for (int np = 0; np < 4; np++) {
                const uint32_t b = Bbase + (uint32_t)(np * 1024) + cb;
                uint32_t bh0[2], bh1[2], bl0[2], bl1[2];
                ldmx4(bh0[0], bh0[1], bh1[0], bh1[1], b);
                ldmx4(bl0[0], bl0[1], bl1[0], bl1[1], b + 16384);
                const int nf = np * 2;
                // 6 passes of 4 independent accumulators: same-acc distance = 8
#pragma unroll
                for (int mf = 0; mf < 4; mf++) mma16816(c[mf][nf],     ah[mf], bh0);
#pragma unroll
                for (int mf = 0; mf < 4; mf++) mma16816(c[mf][nf + 1], ah[mf], bh1);
#pragma unroll
                for (int mf = 0; mf < 4; mf++) mma16816(c[mf][nf],     ah[mf], bl0);
#pragma unroll
                for (int mf = 0; mf < 4; mf++) mma16816(c[mf][nf + 1], ah[mf], bl1);
#pragma unroll
                for (int mf = 0; mf < 4; mf++) mma16816(c[mf][nf],     al[mf], bh0);
#pragma unroll
                for (int mf = 0; mf < 4; mf++) mma16816(c[mf][nf + 1], al[mf], bh1);
            }
        }
    }

    // ---- epilogue ----
    const int group = lane >> 2;
    const int tq    = lane & 3;
#pragma unroll
    for (int mf = 0; mf < 4; mf++) {
#pragma unroll
        for (int nf = 0; nf < 8; nf++) {
            const int ncol = wcol * 64 + nf * 8 + tq * 2;
#pragma unroll
            for (int half = 0; half < 2; half++) {
                const int mrow = wrow * 64 + mf * 16 + group + half * 8;
                const int m = row0 + mrow;
                if (MODE == 0) {
                    __nv_bfloat16 *dh, *dl;
                    float sc;
                    if (z == 0)      { dh = g_qh; dl = g_ql; sc = 0.125f; }
                    else if (z == 1) { dh = g_kh; dl = g_kl; sc = 1.0f;   }
                    else             { dh = g_vh; dl = g_vl; sc = 1.0f;   }
                    const float v0 = c[mf][nf][half * 2]     * sc;
                    const float v1 = c[mf][nf][half * 2 + 1] * sc;
                    uint32_t hi, lo;
                    split2(v0, v1, hi, lo);
                    const int n = col0 + ncol;
                    const int b = m >> 11;
                    const int t = m & (T_ - 1);
                    const int h = n >> 6;
                    const int d = n & 63;
                    const size_t idx = (((size_t)(b * H_ + h) * T_) + t) * HD_ + d;
                    *(uint32_t*)&dh[idx] = hi;
                    *(uint32_t*)&dl[idx] = lo;
                } else {
                    const float2 v2 = make_float2(c[mf][nf][half * 2],
                                                  c[mf][nf][half * 2 + 1]);
                    *(float2*)&out[(size_t)m * C_ + col0 + ncol] = v2;
                }
            }
        }
    }
}

// ---------------------------------------------------------------------------
// Tensor-core sliding-window flash attention. Same as round 9 but MMA issue
// alternates between independent accumulators (and mma is schedulable).
// ---------------------------------------------------------------------------
#define ATT_STAGE  32768                          // Kh,Kl,Vh,Vl @ 64x128B
#define ATT_SMEM   (3 * ATT_STAGE)                // 98304
#define MASKV      (-3.3e38f)

__global__ void __launch_bounds__(256, 2)
attn_mma()
{
    extern __shared__ char sraw[];
    const uint32_t ST = smem_u32(sraw);
    const uint32_t Qb = ST + 2 * ATT_STAGE;       // aliases stage 2

    const int bh  = blockIdx.y;
    const int q0  = blockIdx.x * 128;
    const int tid = threadIdx.x;
    const int w    = tid >> 5;
    const int lane = tid & 31;

    // ---- Q staging into the stage-2 region (consumed before its 1st write) ----
    {
        const __nv_bfloat16* qh = g_qh + ((size_t)bh * T_ + q0) * HD_;
        const __nv_bfloat16* ql = g_ql + ((size_t)bh * T_ + q0) * HD_;
#pragma unroll
        for (int t = 0; t < 4; t++) {
            const int slot = tid + t * 256;
            const int row = slot >> 3, ch = slot & 7;
            const uint32_t so = (uint32_t)(row * 128 + ((ch ^ (row & 7)) << 4));
            const size_t   go = (size_t)row * HD_ + ch * 8;
            cp16(Qb +         so, qh + go);
            cp16(Qb + 16384 + so, ql + go);
        }
        cp_commit();
    }

    int kstart = q0 - (WIN_ - 1);
    if (kstart < 0) kstart = 0;
    kstart &= ~63;
    int kend = q0 + 128 + (WIN_ - 1);
    if (kend > T_) kend = T_;
    const int ntiles = (kend - kstart + 63) >> 6;

    auto load_stage = [&](int i) {
        const int kb = kstart + i * 64;
        if (kb < kend) {
            const uint32_t Sb = ST + (uint32_t)(i % 3) * ATT_STAGE;
            const size_t gb = ((size_t)bh * T_ + kb) * HD_;
#pragma unroll
            for (int t = 0; t < 2; t++) {
                const int slot = tid + t * 256;
                const int row = slot >> 3, ch = slot & 7;
                const uint32_t so = (uint32_t)(row * 128 + ((ch ^ (row & 7)) << 4));
                const size_t   go = gb + (size_t)row * HD_ + ch * 8;
                cp16(Sb +         so, g_kh + go);
                cp16(Sb +  8192 + so, g_kl + go);
                cp16(Sb + 16384 + so, g_vh + go);
                cp16(Sb + 24576 + so, g_vl + go);
            }
        }
        cp_commit();
    };

    load_stage(0);
    load_stage(1);
    cp_wait2();              // Q ready (stages 0,1 may still be in flight)
    __syncthreads();

    // ---- Q fragments to registers ----
    uint32_t qfh[4][4], qfl[4][4];
    {
        const uint32_t qRow = (uint32_t)((w * 16 + (lane & 15)) * 128);
        const uint32_t qSw  = (uint32_t)((lane & 7) << 4);
        const uint32_t qCb  = (uint32_t)((lane >> 4) << 4);
#pragma unroll
        for (int ks = 0; ks < 4; ks++) {
            const uint32_t a = Qb + qRow + ((qCb + (uint32_t)(ks * 32)) ^ qSw);
            ldmx4(qfh[ks][0], qfh[ks][1], qfh[ks][2], qfh[ks][3], a);
            ldmx4(qfl[ks][0], qfl[ks][1], qfl[ks][2], qfl[ks][3], a + 16384);
        }
    }
    __syncthreads();         // all warps done reading Q before stage 2 refill

    float m0 = MASKV, m1 = MASKV, l0 = 0.f, l1 = 0.f;
    float o[8][4];
#pragma unroll
    for (int nf = 0; nf < 8; nf++)
#pragma unroll
        for (int e = 0; e < 4; e++) o[nf][e] = 0.f;

    const int g  = lane >> 2;
    const int tq = lane & 3;
    const int qr0 = q0 + w * 16 + g;

    const int      rK   = (lane & 7) + ((lane & 16) >> 1);
    const uint32_t kRow = (uint32_t)(rK * 128);
    const uint32_t kSw  = (uint32_t)((rK & 7) << 4);
    const uint32_t kCb  = (uint32_t)((lane & 8) << 1);            // 0 or 16
    const int      rV   = lane & 15;
    const uint32_t vRow = (uint32_t)(rV * 128);
    const uint32_t vSw  = (uint32_t)((rV & 7) << 4);
    const uint32_t vCb  = (uint32_t)(lane & 16);                  // 0 or 16

    for (int i = 0; i < ntiles; i++) {
        cp_wait1();
        __syncthreads();
        load_stage(i + 2);   // overwrites stage consumed at i-1 (or Q region at i=0)

        const uint32_t Sb = ST + (uint32_t)(i % 3) * ATT_STAGE;
        const int kb = kstart + i * 64;

        // ---- S = Q K^T (hi/lo split, alternating accumulators) ----
        float c[8][4];
#pragma unroll
        for (int nf = 0; nf < 8; nf++)
#pragma unroll
            for (int e = 0; e < 4; e++) c[nf][e] = 0.f;

#pragma unroll
        for (int ks = 0; ks < 4; ks++) {
            const uint32_t cc = (kCb + (uint32_t)(ks * 32)) ^ kSw;
#pragma unroll
            for (int np = 0; np < 4; np++) {
                const uint32_t addr = Sb + (uint32_t)(np * 2048) + kRow + cc;
                uint32_t b0[2], b1[2], c0[2], c1[2];
                ldmx4(b0[0], b0[1], b1[0], b1[1], addr);
                ldmx4(c0[0], c0[1], c1[0], c1[1], addr + 8192);
                mma16816(c[2*np],     qfh[ks], b0);
                mma16816(c[2*np + 1], qfh[ks], b1);
                mma16816(c[2*np],     qfh[ks], c0);
                mma16816(c[2*np + 1], qfh[ks], c1);
                mma16816(c[2*np],     qfl[ks], b0);
                mma16816(c[2*np + 1], qfl[ks], b1);
            }
        }

        // ---- mask (edge tiles only) ----
        if (kb < q0 - 384 || kb > q0 + 448) {
#pragma unroll
            for (int nf = 0; nf < 8; nf++)
#pragma unroll
                for (int e = 0; e < 4; e++) {
                    const int key = kb + nf * 8 + tq * 2 + (e & 1);
                    const int qq  = qr0 + ((e >> 1) << 3);
                    const int d   = qq - key;
                    if (d > (WIN_ - 1) || d < -(WIN_ - 1)) c[nf][e] = MASKV;
                }
        }

        // ---- online softmax on fragments ----
        float rm0 = MASKV, rm1 = MASKV;
#pragma unroll
        for (int nf = 0; nf < 8; nf++) {
            rm0 = fmaxf(rm0, fmaxf(c[nf][0], c[nf][1]));
            rm1 = fmaxf(rm1, fmaxf(c[nf][2], c[nf][3]));
        }
        rm0 = fmaxf(rm0, __shfl_xor_sync(0xffffffff, rm0, 1));
        rm0 = fmaxf(rm0, __shfl_xor_sync(0xffffffff, rm0, 2));
        rm1 = fmaxf(rm1, __shfl_xor_sync(0xffffffff, rm1, 1));
        rm1 = fmaxf(rm1, __shfl_xor_sync(0xffffffff, rm1, 2));

        const float mn0 = fmaxf(m0, rm0);
        const float mn1 = fmaxf(m1, rm1);
        const float cor0 = __expf(m0 - mn0);
        const float cor1 = __expf(m1 - mn1);
        m0 = mn0; m1 = mn1;
        l0 *= cor0; l1 *= cor1;
#pragma unroll
        for (int nf = 0; nf < 8; nf++) {
            o[nf][0] *= cor0; o[nf][1] *= cor0;
            o[nf][2] *= cor1; o[nf][3] *= cor1;
        }
        float ps0 = 0.f, ps1 = 0.f;
#pragma unroll
        for (int nf = 0; nf < 8; nf++) {
            c[nf][0] = __expf(c[nf][0] - mn0);
            c[nf][1] = __expf(c[nf][1] - mn0);
            c[nf][2] = __expf(c[nf][2] - mn1);
            c[nf][3] = __expf(c[nf][3] - mn1);
            ps0 += c[nf][0] + c[nf][1];
            ps1 += c[nf][2] + c[nf][3];
        }
        l0 += ps0; l1 += ps1;

        // ---- O += P V (hi/lo split, alternating accumulators) ----
        const uint32_t Vb = Sb + 16384;
#pragma unroll
        for (int ks = 0; ks < 4; ks++) {
            uint32_t ah[4], al[4];
            split2(c[2*ks][0],     c[2*ks][1],     ah[0], al[0]);
            split2(c[2*ks][2],     c[2*ks][3],     ah[1], al[1]);
            split2(c[2*ks + 1][0], c[2*ks + 1][1], ah[2], al[2]);
            split2(c[2*ks + 1][2], c[2*ks + 1][3], ah[3], al[3]);
#pragma unroll
            for (int n2 = 0; n2 < 4; n2++) {
                const uint32_t va = Vb + (uint32_t)(ks * 2048) + vRow +
                                    ((vCb + (uint32_t)(n2 * 32)) ^ vSw);
                uint32_t vh0[2], vh1[2], vl0[2], vl1[2];
                ldmx4t(vh0[0], vh0[1], vh1[0], vh1[1], va);
                ldmx4t(vl0[0], vl0[1], vl1[0], vl1[1], va + 8192);
                mma16816(o[2*n2],     ah, vh0);
                mma16816(o[2*n2 + 1], ah, vh1);
                mma16816(o[2*n2],     ah, vl0);
                mma16816(o[2*n2 + 1], ah, vl1);
                mma16816(o[2*n2],     al, vh0);
                mma16816(o[2*n2 + 1], al, vh1);
            }
        }
    }

    // ---- finalize ----
    l0 += __shfl_xor_sync(0xffffffff, l0, 1);
    l0 += __shfl_xor_sync(0xffffffff, l0, 2);
    l1 += __shfl_xor_sync(0xffffffff, l1, 1);
    l1 += __shfl_xor_sync(0xffffffff, l1, 2);
    const float inv0 = 1.f / l0;
    const float inv1 = 1.f / l1;

    const int b = bh >> 4, h = bh & 15;
    const size_t r0 = (size_t)(b * T_ + qr0) * C_ + h * HD_ + tq * 2;
    const size_t r1 = r0 + (size_t)8 * C_;
#pragma unroll
    for (int nf = 0; nf < 8; nf++) {
        uint32_t hi, lo;
        split2(o[nf][0] * inv0, o[nf][1] * inv0, hi, lo);
        *(uint32_t*)&g_att_hi[r0 + nf * 8] = hi;
        *(uint32_t*)&g_att_lo[r0 + nf * 8] = lo;
        split2(o[nf][2] * inv1, o[nf][3] * inv1, hi, lo);
        *(uint32_t*)&g_att_hi[r1 + nf * 8] = hi;
        *(uint32_t*)&g_att_lo[r1 + nf * 8] = lo;
    }
}

// ---------------------------------------------------------------------------
extern "C" void kernel_launch(void* const* d_in, const int* in_sizes, int n_in,
                              void* d_out, int out_size)
{
    const float* x  = (const float*)d_in[0];
    const float* Wq = (const float*)d_in[1];
    const float* Wk = (const float*)d_in[2];
    const float* Wv = (const float*)d_in[3];
    const float* Wo = (const float*)d_in[4];
    float* out = (float*)d_out;

    cudaFuncSetAttribute(gemm_mma<0>, cudaFuncAttributeMaxDynamicSharedMemorySize, GEMM_SMEM);
    cudaFuncSetAttribute(gemm_mma<1>, cudaFuncAttributeMaxDynamicSharedMemorySize, GEMM_SMEM);
    cudaFuncSetAttribute(attn_mma,    cudaFuncAttributeMaxDynamicSharedMemorySize, ATT_SMEM);

    conv_kernel<<<8192, 256>>>(x, Wq, Wk, Wv, Wo);

    dim3 qkv_grid(C_ / 256, M_ / 128, 3);    // (4, 32, 3)
    gemm_mma<0><<<qkv_grid, 256, GEMM_SMEM>>>(nullptr);

    dim3 attn_grid(T_ / 128, B_ * H_);       // (16, 32)
    attn_mma<<<attn_grid, 256, ATT_SMEM>>>();

    dim3 out_grid(C_ / 256, M_ / 128, 1);    // (4, 32)
    gemm_mma<1><<<out_grid, 256, GEMM_SMEM>>>(out);
}

// round 11
// speedup vs baseline: 2.5368x; 2.5368x over previous
#include <cuda_runtime.h>
#include <cuda_fp16.h>
#include <math.h>
#include <stdint.h>

#define B_   2
#define T_   2048
#define C_   1024
#define H_   16
#define HD_  64
#define WIN_ 512
#define M_   (B_ * T_)

// ---------------------------------------------------------------------------
// Device scratch (allocation-free) — single fp16 everywhere
// ---------------------------------------------------------------------------
__device__ __half g_q16[(size_t)B_ * H_ * T_ * HD_];
__device__ __half g_k16[(size_t)B_ * H_ * T_ * HD_];
__device__ __half g_v16[(size_t)B_ * H_ * T_ * HD_];
__device__ __half g_x16[(size_t)M_ * C_];
__device__ __half g_w16[(size_t)4 * C_ * C_];   // Wq,Wk,Wv,Wo stacked
__device__ __half g_att16[(size_t)M_ * C_];

// ---------------------------------------------------------------------------
// PTX helpers — compute_80-compatible only
// ---------------------------------------------------------------------------
__device__ __forceinline__ uint32_t smem_u32(const void* p) {
    uint32_t a;
    asm("{ .reg .u64 t; cvta.to.shared.u64 t, %1; cvt.u32.u64 %0, t; }"
        : "=r"(a) : "l"(p));
    return a;
}

__device__ __forceinline__ void cp16(uint32_t s, const void* g) {
    asm volatile("cp.async.cg.shared.global [%0], [%1], 16;" :: "r"(s), "l"(g));
}
__device__ __forceinline__ void cp_commit() { asm volatile("cp.async.commit_group;"); }
__device__ __forceinline__ void cp_wait1()  { asm volatile("cp.async.wait_group 1;" ::: "memory"); }
__device__ __forceinline__ void cp_wait2()  { asm volatile("cp.async.wait_group 2;" ::: "memory"); }

__device__ __forceinline__ void ldmx4(uint32_t& r0, uint32_t& r1, uint32_t& r2, uint32_t& r3,
                                      uint32_t addr) {
    asm volatile("ldmatrix.sync.aligned.m8n8.x4.shared.b16 {%0,%1,%2,%3}, [%4];"
                 : "=r"(r0), "=r"(r1), "=r"(r2), "=r"(r3) : "r"(addr));
}
__device__ __forceinline__ void ldmx4t(uint32_t& r0, uint32_t& r1, uint32_t& r2, uint32_t& r3,
                                       uint32_t addr) {
    asm volatile("ldmatrix.sync.aligned.m8n8.x4.trans.shared.b16 {%0,%1,%2,%3}, [%4];"
                 : "=r"(r0), "=r"(r1), "=r"(r2), "=r"(r3) : "r"(addr));
}

// fp16 MMA, fp32 accumulate. Not volatile — ptxas may schedule.
__device__ __forceinline__ void mma16816(float* c, const uint32_t* a, const uint32_t* b) {
    asm("mma.sync.aligned.m16n8k16.row.col.f32.f16.f16.f32 "
        "{%0,%1,%2,%3}, {%4,%5,%6,%7}, {%8,%9}, {%0,%1,%2,%3};"
        : "+f"(c[0]), "+f"(c[1]), "+f"(c[2]), "+f"(c[3])
        : "r"(a[0]), "r"(a[1]), "r"(a[2]), "r"(a[3]), "r"(b[0]), "r"(b[1]));
}

// pack two fp32 into fp16x2 (a -> low half, b -> high half)
__device__ __forceinline__ uint32_t pk16(float a, float b) {
    uint32_t r;
    asm("cvt.rn.f16x2.f32 %0, %1, %2;" : "=r"(r) : "f"(b), "f"(a));
    return r;
}

// ---------------------------------------------------------------------------
// fp32 -> fp16 conversion (x and the 4 weight matrices)
// ---------------------------------------------------------------------------
__global__ __launch_bounds__(256)
void conv_kernel(const float* __restrict__ x,
                 const float* __restrict__ wq, const float* __restrict__ wk,
                 const float* __restrict__ wv, const float* __restrict__ wo)
{
    const int i = blockIdx.x * 256 + threadIdx.x;   // float4 index
    const float* src;
    __half* dst;
    size_t off;
    if (i < 1048576) {
        src = x + (size_t)i * 4;
        dst = g_x16; off = (size_t)i * 4;
    } else {
        const int r = i - 1048576;
        const int w = r >> 18;
        const float* ws = (w == 0) ? wq : (w == 1) ? wk : (w == 2) ? wv : wo;
        src = ws + (size_t)(r & 262143) * 4;
        dst = g_w16; off = (size_t)r * 4;
    }
    const float4 v = *(const float4*)src;
    *(uint32_t*)(dst + off)     = pk16(v.x, v.y);
    *(uint32_t*)(dst + off + 2) = pk16(v.z, v.w);
}

// ---------------------------------------------------------------------------
// fp16 mma.sync GEMM (single MMA per fragment pair).
// CTA 128x128, BK=64, 256 threads: 8 warps as 4(M) x 2(N), warp tile 32x64.
// 128 B rows, SW128 XOR swizzle (chunk ^ (row&7)). 3-stage cp.async pipeline,
// one __syncthreads per chunk. smem = 3*32768 = 98304 -> 2 CTAs/SM.
// MODE 0: out -> fp16 q/k/v in [B,H,T,hd]; Q scaled by 1/8.
// MODE 1: A = g_att16, W = Wo; out = fp32 [M,C].
// ---------------------------------------------------------------------------
#define STG_BYTES 32768              // A 16KB @0, B 16KB @16384
#define GEMM_SMEM (3 * STG_BYTES)    // 98304

template <int MODE>
__global__ void __launch_bounds__(256, 2)
gemm_mma(float* __restrict__ out)
{
    extern __shared__ char smem_raw[];
    const uint32_t smem = smem_u32(smem_raw);

    const int tid  = threadIdx.x;
    const int wid  = tid >> 5;
    const int lane = tid & 31;
    const int col0 = blockIdx.x * 128;
    const int row0 = blockIdx.y * 128;
    const int z    = blockIdx.z;

    const int wrow = wid & 3;        // M: 4 warps x 32
    const int wcol = wid >> 2;       // N: 2 warps x 64

    const __half* A16 = (MODE == 0) ? g_x16 : g_att16;
    const size_t woff = (MODE == 0 ? (size_t)z : 3) * ((size_t)C_ * C_);

    const __half* a16 = A16 + (size_t)row0 * C_;
    const __half* b16 = g_w16 + woff + (size_t)col0 * C_;

    auto load_stage = [&](int chunk, int s) {
        const int k0 = chunk * 64;
        const uint32_t st = smem + (uint32_t)s * STG_BYTES;
#pragma unroll
        for (int q = 0; q < 4; q++) {
            const int slot = tid + q * 256;         // 0..1023
            const int rr = slot >> 3;               // row 0..127
            const int ch = slot & 7;                // 16B chunk 0..7
            const uint32_t so = (uint32_t)(rr * 128 + ((ch ^ (rr & 7)) << 4));
            const size_t   go = (size_t)rr * C_ + k0 + ch * 8;
            cp16(st +         so, a16 + go);
            cp16(st + 16384 + so, b16 + go);
        }
        cp_commit();
    };

    float c[2][8][4];
#pragma unroll
    for (int mf = 0; mf < 2; mf++)
#pragma unroll
        for (int nf = 0; nf < 8; nf++)
#pragma unroll
            for (int e = 0; e < 4; e++) c[mf][nf][e] = 0.f;

    // ldmatrix lane pieces (row offset + swizzle key, bytes)
    const int      rA    = lane & 15;
    const uint32_t aRow  = (uint32_t)(rA * 128);
    const uint32_t aSw   = (uint32_t)((rA & 7) << 4);
    const uint32_t aCb   = (uint32_t)((lane >> 4) << 4);          // 0 or 16
    const int      rB    = (lane & 7) + ((lane & 16) >> 1);
    const uint32_t bRow  = (uint32_t)(rB * 128);
    const uint32_t bSw   = (uint32_t)((rB & 7) << 4);
    const uint32_t bCb   = (uint32_t)((lane & 8) << 1);           // 0 or 16

    load_stage(0, 0);
    load_stage(1, 1);

    for (int ck = 0; ck < 16; ck++) {
        cp_wait1();
        __syncthreads();
        if (ck + 2 < 16) load_stage(ck + 2, (ck + 2) % 3);
        else             cp_commit();                  // keep group count uniform

        const uint32_t st = smem + (uint32_t)(ck % 3) * STG_BYTES;
        const uint32_t Abase = st + (uint32_t)(wrow * 4096) + aRow;           // 32 rows
        const uint32_t Bbase = st + 16384 + (uint32_t)(wcol * 8192) + bRow;   // 64 rows

#pragma unroll
        for (int k16 = 0; k16 < 4; k16++) {
            const uint32_t ca = ((aCb + (uint32_t)(k16 * 32)) ^ aSw);
            const uint32_t cb = ((bCb + (uint32_t)(k16 * 32)) ^ bSw);
            uint32_t af[2][4];
#pragma unroll
            for (int mf = 0; mf < 2; mf++) {
                const uint32_t a = Abase + (uint32_t)(mf * 2048) + ca;
                ldmx4(af[mf][0], af[mf][1], af[mf][2], af[mf][3], a);
            }
#pragma unroll
            for (int np = 0; np < 4; np++) {
                const uint32_t b = Bbase + (uint32_t)(np * 2048) + cb;
                uint32_t b0[2], b1[2];
                ldmx4(b0[0], b0[1], b1[0], b1[1], b);
                const int nf = np * 2;
                mma16816(c[0][nf],     af[0], b0);
                mma16816(c[1][nf],     af[1], b0);
                mma16816(c[0][nf + 1], af[0], b1);
                mma16816(c[1][nf + 1], af[1], b1);
            }
        }
    }

    // ---- epilogue ----
    const int group = lane >> 2;
    const int tq    = lane & 3;
#pragma unroll
    for (int mf = 0; mf < 2; mf++) {
#pragma unroll
        for (int nf = 0; nf < 8; nf++) {
            const int ncol = wcol * 64 + nf * 8 + tq * 2;
#pragma unroll
            for (int half = 0; half < 2; half++) {
                const int mrow = wrow * 32 + mf * 16 + group + half * 8;
                const int m = row0 + mrow;
                if (MODE == 0) {
                    __half* dst;
                    float sc;
                    if (z == 0)      { dst = g_q16; sc = 0.125f; }
                    else if (z == 1) { dst = g_k16; sc = 1.0f;   }
                    else             { dst = g_v16; sc = 1.0f;   }
                    const uint32_t hv = pk16(c[mf][nf][half * 2]     * sc,
                                             c[mf][nf][half * 2 + 1] * sc);
                    const int n = col0 + ncol;
                    const int b = m >> 11;
                    const int t = m & (T_ - 1);
                    const int h = n >> 6;
                    const int d = n & 63;
                    const size_t idx = (((size_t)(b * H_ + h) * T_) + t) * HD_ + d;
                    *(uint32_t*)&dst[idx] = hv;
                } else {
                    const float2 v2 = make_float2(c[mf][nf][half * 2],
                                                  c[mf][nf][half * 2 + 1]);
                    *(float2*)&out[(size_t)m * C_ + col0 + ncol] = v2;
                }
            }
        }
    }
}

// ---------------------------------------------------------------------------
// fp16 tensor-core sliding-window flash attention.
// CTA: 128 queries x one (b,h); 8 warps x 16 query rows; key tiles of 64.
// 128 B rows, SW128 swizzle. 3-stage cp.async pipeline (16 KB stages), one
// __syncthreads per tile; Q (16 KB) aliases stage 2. 2 CTAs/SM.
// ---------------------------------------------------------------------------
#define ATT_STAGE  16384                          // K @0 (8KB), V @8192 (8KB)
#define ATT_SMEM   (3 * ATT_STAGE)                // 49152
#define MASKV      (-3.3e38f)

__global__ void __launch_bounds__(256, 2)
attn_mma()
{
    extern __shared__ char sraw[];
    const uint32_t ST = smem_u32(sraw);
    const uint32_t Qb = ST + 2 * ATT_STAGE;       // aliases stage 2

    const int bh  = blockIdx.y;
    const int q0  = blockIdx.x * 128;
    const int tid = threadIdx.x;
    const int w    = tid >> 5;
    const int lane = tid & 31;

    // ---- Q staging into the stage-2 region (consumed before its 1st write) ----
    {
        const __half* q16 = g_q16 + ((size_t)bh * T_ + q0) * HD_;
#pragma unroll
        for (int t = 0; t < 4; t++) {
            const int slot = tid + t * 256;        // 0..1023
            const int row = slot >> 3, ch = slot & 7;
            const uint32_t so = (uint32_t)(row * 128 + ((ch ^ (row & 7)) << 4));
            cp16(Qb + so, q16 + (size_t)row * HD_ + ch * 8);
        }
        cp_commit();
    }

    int kstart = q0 - (WIN_ - 1);
    if (kstart < 0) kstart = 0;
    kstart &= ~63;
    int kend = q0 + 128 + (WIN_ - 1);
    if (kend > T_) kend = T_;
    const int ntiles = (kend - kstart + 63) >> 6;

    auto load_stage = [&](int i) {
        const int kb = kstart + i * 64;
        if (kb < kend) {
            const uint32_t Sb = ST + (uint32_t)(i % 3) * ATT_STAGE;
            const size_t gb = ((size_t)bh * T_ + kb) * HD_;
#pragma unroll
            for (int t = 0; t < 2; t++) {
                const int slot = tid + t * 256;    // 0..511
                const int row = slot >> 3, ch = slot & 7;
                const uint32_t so = (uint32_t)(row * 128 + ((ch ^ (row & 7)) << 4));
                const size_t   go = gb + (size_t)row * HD_ + ch * 8;
                cp16(Sb +        so, g_k16 + go);
                cp16(Sb + 8192 + so, g_v16 + go);
            }
        }
        cp_commit();
    };

    load_stage(0);
    load_stage(1);
    cp_wait2();              // Q ready (stages 0,1 may still be in flight)
    __syncthreads();

    // ---- Q fragments to registers ----
    uint32_t qf[4][4];
    {
        const uint32_t qRow = (uint32_t)((w * 16 + (lane & 15)) * 128);
        const uint32_t qSw  = (uint32_t)((lane & 7) << 4);
        const uint32_t qCb  = (uint32_t)((lane >> 4) << 4);
#pragma unroll
        for (int ks = 0; ks < 4; ks++) {
            const uint32_t a = Qb + qRow + ((qCb + (uint32_t)(ks * 32)) ^ qSw);
            ldmx4(qf[ks][0], qf[ks][1], qf[ks][2], qf[ks][3], a);
        }
    }
    __syncthreads();         // all warps done reading Q before stage 2 refill

    float m0 = MASKV, m1 = MASKV, l0 = 0.f, l1 = 0.f;
    float o[8][4];
#pragma unroll
    for (int nf = 0; nf < 8; nf++)
#pragma unroll
        for (int e = 0; e < 4; e++) o[nf][e] = 0.f;

    const int g  = lane >> 2;
    const int tq = lane & 3;
    const int qr0 = q0 + w * 16 + g;

    const int      rK   = (lane & 7) + ((lane & 16) >> 1);
    const uint32_t kRow = (uint32_t)(rK * 128);
    const uint32_t kSw  = (uint32_t)((rK & 7) << 4);
    const uint32_t kCb  = (uint32_t)((lane & 8) << 1);            // 0 or 16
    const int      rV   = lane & 15;
    const uint32_t vRow = (uint32_t)(rV * 128);
    const uint32_t vSw  = (uint32_t)((rV & 7) << 4);
    const uint32_t vCb  = (uint32_t)(lane & 16);                  // 0 or 16

    for (int i = 0; i < ntiles; i++) {
        cp_wait1();
        __syncthreads();
        load_stage(i + 2);   // overwrites stage consumed at i-1 (or Q region at i=0)

        const uint32_t Sb = ST + (uint32_t)(i % 3) * ATT_STAGE;
        const int kb = kstart + i * 64;

        // ---- S = Q K^T ----
        float c[8][4];
#pragma unroll
        for (int nf = 0; nf < 8; nf++)
#pragma unroll
            for (int e = 0; e < 4; e++) c[nf][e] = 0.f;

#pragma unroll
        for (int ks = 0; ks < 4; ks++) {
            const uint32_t cc = (kCb + (uint32_t)(ks * 32)) ^ kSw;
#pragma unroll
            for (int np = 0; np < 4; np++) {
                const uint32_t addr = Sb + (uint32_t)(np * 2048) + kRow + cc;
                uint32_t b0[2], b1[2];
                ldmx4(b0[0], b0[1], b1[0], b1[1], addr);
                mma16816(c[2*np],     qf[ks], b0);
                mma16816(c[2*np + 1], qf[ks], b1);
            }
        }

        // ---- mask (edge tiles only) ----
        if (kb < q0 - 384 || kb > q0 + 448) {
#pragma unroll
            for (int nf = 0; nf < 8; nf++)
#pragma unroll
                for (int e = 0; e < 4; e++) {
                    const int key = kb + nf * 8 + tq * 2 + (e & 1);
                    const int qq  = qr0 + ((e >> 1) << 3);
                    const int d   = qq - key;
                    if (d > (WIN_ - 1) || d < -(WIN_ - 1)) c[nf][e] = MASKV;
                }
        }

        // ---- online softmax on fragments ----
        float rm0 = MASKV, rm1 = MASKV;
#pragma unroll
        for (int nf = 0; nf < 8; nf++) {
            rm0 = fmaxf(rm0, fmaxf(c[nf][0], c[nf][1]));
            rm1 = fmaxf(rm1, fmaxf(c[nf][2], c[nf][3]));
        }
        rm0 = fmaxf(rm0, __shfl_xor_sync(0xffffffff, rm0, 1));
        rm0 = fmaxf(rm0, __shfl_xor_sync(0xffffffff, rm0, 2));
        rm1 = fmaxf(rm1, __shfl_xor_sync(0xffffffff, rm1, 1));
        rm1 = fmaxf(rm1, __shfl_xor_sync(0xffffffff, rm1, 2));

        const float mn0 = fmaxf(m0, rm0);
        const float mn1 = fmaxf(m1, rm1);
        const float cor0 = __expf(m0 - mn0);
        const float cor1 = __expf(m1 - mn1);
        m0 = mn0; m1 = mn1;
        l0 *= cor0; l1 *= cor1;
#pragma unroll
        for (int nf = 0; nf < 8; nf++) {
            o[nf][0] *= cor0; o[nf][1] *= cor0;
            o[nf][2] *= cor1; o[nf][3] *= cor1;
        }
        float ps0 = 0.f, ps1 = 0.f;
#pragma unroll
        for (int nf = 0; nf < 8; nf++) {
            c[nf][0] = __expf(c[nf][0] - mn0);
            c[nf][1] = __expf(c[nf][1] - mn0);
            c[nf][2] = __expf(c[nf][2] - mn1);
            c[nf][3] = __expf(c[nf][3] - mn1);
            ps0 += c[nf][0] + c[nf][1];
            ps1 += c[nf][2] + c[nf][3];
        }
        l0 += ps0; l1 += ps1;

        // ---- O += P V ----
        const uint32_t Vb = Sb + 8192;
#pragma unroll
        for (int ks = 0; ks < 4; ks++) {
            uint32_t ah[4];
            ah[0] = pk16(c[2*ks][0],     c[2*ks][1]);
            ah[1] = pk16(c[2*ks][2],     c[2*ks][3]);
            ah[2] = pk16(c[2*ks + 1][0], c[2*ks + 1][1]);
            ah[3] = pk16(c[2*ks + 1][2], c[2*ks + 1][3]);
#pragma unroll
            for (int n2 = 0; n2 < 4; n2++) {
                const uint32_t va = Vb + (uint32_t)(ks * 2048) + vRow +
                                    ((vCb + (uint32_t)(n2 * 32)) ^ vSw);
                uint32_t vh0[2], vh1[2];
                ldmx4t(vh0[0], vh0[1], vh1[0], vh1[1], va);
                mma16816(o[2*n2],     ah, vh0);
                mma16816(o[2*n2 + 1], ah, vh1);
            }
        }
    }

    // ---- finalize ----
    l0 += __shfl_xor_sync(0xffffffff, l0, 1);
    l0 += __shfl_xor_sync(0xffffffff, l0, 2);
    l1 += __shfl_xor_sync(0xffffffff, l1, 1);
    l1 += __shfl_xor_sync(0xffffffff, l1, 2);
    const float inv0 = 1.f / l0;
    const float inv1 = 1.f / l1;

    const int b = bh >> 4, h = bh & 15;
    const size_t r0 = (size_t)(b * T_ + qr0) * C_ + h * HD_ + tq * 2;
    const size_t r1 = r0 + (size_t)8 * C_;
#pragma unroll
    for (int nf = 0; nf < 8; nf++) {
        *(uint32_t*)&g_att16[r0 + nf * 8] = pk16(o[nf][0] * inv0, o[nf][1] * inv0);
        *(uint32_t*)&g_att16[r1 + nf * 8] = pk16(o[nf][2] * inv1, o[nf][3] * inv1);
    }
}

// ---------------------------------------------------------------------------
extern "C" void kernel_launch(void* const* d_in, const int* in_sizes, int n_in,
                              void* d_out, int out_size)
{
    const float* x  = (const float*)d_in[0];
    const float* Wq = (const float*)d_in[1];
    const float* Wk = (const float*)d_in[2];
    const float* Wv = (const float*)d_in[3];
    const float* Wo = (const float*)d_in[4];
    float* out = (float*)d_out;

    cudaFuncSetAttribute(gemm_mma<0>, cudaFuncAttributeMaxDynamicSharedMemorySize, GEMM_SMEM);
    cudaFuncSetAttribute(gemm_mma<1>, cudaFuncAttributeMaxDynamicSharedMemorySize, GEMM_SMEM);
    cudaFuncSetAttribute(attn_mma,    cudaFuncAttributeMaxDynamicSharedMemorySize, ATT_SMEM);

    conv_kernel<<<8192, 256>>>(x, Wq, Wk, Wv, Wo);

    dim3 qkv_grid(C_ / 128, M_ / 128, 3);    // (8, 32, 3)
    gemm_mma<0><<<qkv_grid, 256, GEMM_SMEM>>>(nullptr);

    dim3 attn_grid(T_ / 128, B_ * H_);       // (16, 32)
    attn_mma<<<attn_grid, 256, ATT_SMEM>>>();

    dim3 out_grid(C_ / 128, M_ / 128, 1);    // (8, 32)
    gemm_mma<1><<<out_grid, 256, GEMM_SMEM>>>(out);
}